// round 1
// baseline (speedup 1.0000x reference)
#include <cuda_runtime.h>

#define N_ROWS  100000
#define C_DIM   1024
#define OUT_DIM 256
#define TOPK_K  8
#define NPAIR   28
#define QDIM_V  2076
#define LN_EPS  1e-5f

// ---------------------------------------------------------------------------
// Device-global scratch (no cudaMalloc allowed)
// ---------------------------------------------------------------------------
__device__ float g_z [(size_t)N_ROWS * C_DIM];   // 409.6 MB  pre-phi LN'd... (raw z, LN applied in pass 2)
__device__ float g_qc[(size_t)N_ROWS * C_DIM];   // cos(pi*tanh(z_ln))
__device__ float g_qs[(size_t)N_ROWS * C_DIM];   // sin(pi*tanh(z_ln))
__device__ float g_colsum [C_DIM];
__device__ float g_colsum2[C_DIM];
__device__ int   g_idx[TOPK_K];

// np.triu_indices(8, 1) — pair order is load-bearing (maps to W_out columns)
__constant__ int c_iu[NPAIR] = {0,0,0,0,0,0,0, 1,1,1,1,1,1, 2,2,2,2,2, 3,3,3,3, 4,4,4, 5,5, 6};
__constant__ int c_ju[NPAIR] = {1,2,3,4,5,6,7, 2,3,4,5,6,7, 3,4,5,6,7, 4,5,6,7, 5,6,7, 6,7, 7};

// ---------------------------------------------------------------------------
// Kernel 0: zero the per-replay column accumulators
// ---------------------------------------------------------------------------
__global__ void zero_stats_kernel() {
    int t = threadIdx.x;
    if (t < C_DIM) { g_colsum[t] = 0.f; g_colsum2[t] = 0.f; }
}

// ---------------------------------------------------------------------------
// Kernel 1: z = x @ W_proj^T + b_proj      (SGEMM NT, 128x128x16, 8x8/thread)
// ---------------------------------------------------------------------------
__global__ __launch_bounds__(256)
void gemm1_kernel(const float* __restrict__ X,
                  const float* __restrict__ W,
                  const float* __restrict__ bias)
{
    __shared__ float As[16][132];   // +4 pad kills store bank conflicts
    __shared__ float Bs[16][132];

    const int tid  = threadIdx.x;
    const int bn   = blockIdx.x;          // 0..7 (C / 128)
    const int bm   = blockIdx.y;          // M tiles
    const int rowL = tid >> 2;            // 0..63
    const int colL = (tid & 3) << 2;      // 0,4,8,12
    const int tr   = tid >> 4;            // 0..15
    const int tc   = tid & 15;            // 0..15
    const int m0   = bm * 128;

    const bool v0 = (m0 + rowL)      < N_ROWS;
    const bool v1 = (m0 + rowL + 64) < N_ROWS;
    const float* xp0 = X + (size_t)(m0 + rowL)          * C_DIM + colL;
    const float* xp1 = X + (size_t)(m0 + rowL + 64)     * C_DIM + colL;
    const float* wp0 = W + (size_t)(bn * 128 + rowL)    * C_DIM + colL;
    const float* wp1 = W + (size_t)(bn * 128 + rowL+64) * C_DIM + colL;

    float acc[8][8];
#pragma unroll
    for (int i = 0; i < 8; i++)
#pragma unroll
        for (int j = 0; j < 8; j++) acc[i][j] = 0.f;

    for (int kt = 0; kt < C_DIM; kt += 16) {
        float4 a0 = v0 ? *(const float4*)(xp0 + kt) : make_float4(0.f,0.f,0.f,0.f);
        float4 a1 = v1 ? *(const float4*)(xp1 + kt) : make_float4(0.f,0.f,0.f,0.f);
        float4 b0 = *(const float4*)(wp0 + kt);
        float4 b1 = *(const float4*)(wp1 + kt);
        As[colL+0][rowL]    = a0.x; As[colL+1][rowL]    = a0.y;
        As[colL+2][rowL]    = a0.z; As[colL+3][rowL]    = a0.w;
        As[colL+0][rowL+64] = a1.x; As[colL+1][rowL+64] = a1.y;
        As[colL+2][rowL+64] = a1.z; As[colL+3][rowL+64] = a1.w;
        Bs[colL+0][rowL]    = b0.x; Bs[colL+1][rowL]    = b0.y;
        Bs[colL+2][rowL]    = b0.z; Bs[colL+3][rowL]    = b0.w;
        Bs[colL+0][rowL+64] = b1.x; Bs[colL+1][rowL+64] = b1.y;
        Bs[colL+2][rowL+64] = b1.z; Bs[colL+3][rowL+64] = b1.w;
        __syncthreads();
#pragma unroll
        for (int k = 0; k < 16; k++) {
            float4 mv0 = *(const float4*)&As[k][tr*8];
            float4 mv1 = *(const float4*)&As[k][tr*8+4];
            float4 nv0 = *(const float4*)&Bs[k][tc*8];
            float4 nv1 = *(const float4*)&Bs[k][tc*8+4];
            float rm[8] = {mv0.x,mv0.y,mv0.z,mv0.w, mv1.x,mv1.y,mv1.z,mv1.w};
            float rn[8] = {nv0.x,nv0.y,nv0.z,nv0.w, nv1.x,nv1.y,nv1.z,nv1.w};
#pragma unroll
            for (int i = 0; i < 8; i++)
#pragma unroll
                for (int j = 0; j < 8; j++)
                    acc[i][j] = fmaf(rm[i], rn[j], acc[i][j]);
        }
        __syncthreads();
    }

#pragma unroll
    for (int i = 0; i < 8; i++) {
        int m = m0 + tr*8 + i;
        if (m < N_ROWS) {
            float* zr = g_z + (size_t)m * C_DIM + bn*128 + tc*8;
            const float* bp = bias + bn*128 + tc*8;
            float4 o0 = make_float4(acc[i][0]+bp[0], acc[i][1]+bp[1],
                                    acc[i][2]+bp[2], acc[i][3]+bp[3]);
            float4 o1 = make_float4(acc[i][4]+bp[4], acc[i][5]+bp[5],
                                    acc[i][6]+bp[6], acc[i][7]+bp[7]);
            ((float4*)zr)[0] = o0;
            ((float4*)zr)[1] = o1;
        }
    }
}

// ---------------------------------------------------------------------------
// Kernel 2: row LayerNorm + phi = pi*tanh -> (cos,sin), fused column stats
//           128 rows per block, 256 threads (each thread owns 4 columns)
// ---------------------------------------------------------------------------
__global__ __launch_bounds__(256)
void ln_phi_kernel(const float* __restrict__ lng, const float* __restrict__ lnb)
{
    const int tid  = threadIdx.x;
    const int lane = tid & 31;
    const int warp = tid >> 5;
    const int row0 = blockIdx.x * 128;
    const int rowEnd = min(row0 + 128, N_ROWS);

    __shared__ float redS[8], redS2[8];
    __shared__ float sMu, sRstd;

    float gv[4], bv[4];
#pragma unroll
    for (int j = 0; j < 4; j++) { gv[j] = lng[tid + j*256]; bv[j] = lnb[tid + j*256]; }

    float cs[4]  = {0.f,0.f,0.f,0.f};
    float cs2[4] = {0.f,0.f,0.f,0.f};

    for (int row = row0; row < rowEnd; row++) {
        const float* zr = g_z + (size_t)row * C_DIM;
        float v[4]; float s = 0.f, s2 = 0.f;
#pragma unroll
        for (int j = 0; j < 4; j++) {
            v[j] = zr[tid + j*256];
            s += v[j]; s2 += v[j]*v[j];
        }
#pragma unroll
        for (int off = 16; off; off >>= 1) {
            s  += __shfl_xor_sync(0xffffffffu, s,  off);
            s2 += __shfl_xor_sync(0xffffffffu, s2, off);
        }
        if (lane == 0) { redS[warp] = s; redS2[warp] = s2; }
        __syncthreads();
        if (tid == 0) {
            float S = 0.f, S2 = 0.f;
#pragma unroll
            for (int w = 0; w < 8; w++) { S += redS[w]; S2 += redS2[w]; }
            float mu = S * (1.f / C_DIM);
            sMu = mu;
            sRstd = rsqrtf(S2 * (1.f / C_DIM) - mu*mu + LN_EPS);
        }
        __syncthreads();
        const float mu = sMu, rstd = sRstd;
        float* qcr = g_qc + (size_t)row * C_DIM;
        float* qsr = g_qs + (size_t)row * C_DIM;
#pragma unroll
        for (int j = 0; j < 4; j++) {
            float zl = (v[j] - mu) * rstd * gv[j] + bv[j];
            cs[j] += zl; cs2[j] += zl * zl;
            float phi = 3.14159265358979323846f * tanhf(zl);
            float sn, cn; sincosf(phi, &sn, &cn);
            qcr[tid + j*256] = cn;
            qsr[tid + j*256] = sn;
        }
    }
#pragma unroll
    for (int j = 0; j < 4; j++) {
        atomicAdd(&g_colsum [tid + j*256], cs[j]);
        atomicAdd(&g_colsum2[tid + j*256], cs2[j]);
    }
}

// ---------------------------------------------------------------------------
// Kernel 3: column variance (ddof=1) + top-8 (ties -> lower index, matches
//           jax.lax.top_k ordering). One block.
// ---------------------------------------------------------------------------
__global__ void topk_kernel()
{
    __shared__ float svar[C_DIM];
    const int tid = threadIdx.x;
    for (int c = tid; c < C_DIM; c += 256) {
        float s = g_colsum[c], s2 = g_colsum2[c];
        float mean = s * (1.f / N_ROWS);
        svar[c] = (s2 - s * mean) * (1.f / (N_ROWS - 1));
    }
    __syncthreads();
    if (tid < 32) {
        for (int p = 0; p < TOPK_K; p++) {
            float bvv = -3.0e38f; int bii = C_DIM;
            for (int c = tid; c < C_DIM; c += 32) {
                float vv = svar[c];
                if (vv > bvv || (vv == bvv && c < bii)) { bvv = vv; bii = c; }
            }
#pragma unroll
            for (int off = 16; off; off >>= 1) {
                float ov = __shfl_xor_sync(0xffffffffu, bvv, off);
                int   oi = __shfl_xor_sync(0xffffffffu, bii, off);
                if (ov > bvv || (ov == bvv && oi < bii)) { bvv = ov; bii = oi; }
            }
            if (tid == 0) { g_idx[p] = bii; svar[bii] = -3.0e38f; }
            __syncwarp();
        }
    }
}

// ---------------------------------------------------------------------------
// Kernel 4: out = LN( alpha*( Qc@Wc^T + Qs@Ws^T + qint@Wi^T ) + b_out )
//           64x256 tile, BK=16, 8x8/thread; warp = 8 full rows -> fused LN
// ---------------------------------------------------------------------------
__global__ __launch_bounds__(256)
void gemm2_kernel(const float* __restrict__ Wout,
                  const float* __restrict__ bout,
                  const float* __restrict__ alphap,
                  const float* __restrict__ og,
                  const float* __restrict__ ob,
                  float* __restrict__ Out)
{
    __shared__ float buf[9984];                 // union: GEMM tiles / interaction stage
    float* As = buf;                            // [16][68] = 1088 floats
    float* Bs = buf + 16*68;                    // [16][256] = 4096 floats

    const int tid  = threadIdx.x;
    const int row0 = blockIdx.x * 64;
    const int tr   = tid >> 5;                  // 0..7 (warp id = row group)
    const int tc   = tid & 31;                  // 0..31
    const int rowA = tid >> 2;                  // 0..63
    const int colA = (tid & 3) << 2;            // 0,4,8,12
    const bool av  = (row0 + rowA) < N_ROWS;

    float acc[8][8];
#pragma unroll
    for (int i = 0; i < 8; i++)
#pragma unroll
        for (int j = 0; j < 8; j++) acc[i][j] = 0.f;

    for (int ph = 0; ph < 2; ph++) {
        const float* Ap   = (ph == 0) ? g_qc : g_qs;
        const float* wRow = Wout + (size_t)tid * QDIM_V + ph * 1024;
        const float* aRow = Ap + (size_t)(row0 + rowA) * C_DIM + colA;

        for (int kt = 0; kt < 1024; kt += 16) {
            float4 a4 = av ? *(const float4*)(aRow + kt) : make_float4(0.f,0.f,0.f,0.f);
            float4 w0 = *(const float4*)(wRow + kt + 0);
            float4 w1 = *(const float4*)(wRow + kt + 4);
            float4 w2 = *(const float4*)(wRow + kt + 8);
            float4 w3 = *(const float4*)(wRow + kt + 12);
            As[(colA+0)*68 + rowA] = a4.x;
            As[(colA+1)*68 + rowA] = a4.y;
            As[(colA+2)*68 + rowA] = a4.z;
            As[(colA+3)*68 + rowA] = a4.w;
            Bs[ 0*256 + tid] = w0.x; Bs[ 1*256 + tid] = w0.y;
            Bs[ 2*256 + tid] = w0.z; Bs[ 3*256 + tid] = w0.w;
            Bs[ 4*256 + tid] = w1.x; Bs[ 5*256 + tid] = w1.y;
            Bs[ 6*256 + tid] = w1.z; Bs[ 7*256 + tid] = w1.w;
            Bs[ 8*256 + tid] = w2.x; Bs[ 9*256 + tid] = w2.y;
            Bs[10*256 + tid] = w2.z; Bs[11*256 + tid] = w2.w;
            Bs[12*256 + tid] = w3.x; Bs[13*256 + tid] = w3.y;
            Bs[14*256 + tid] = w3.z; Bs[15*256 + tid] = w3.w;
            __syncthreads();
#pragma unroll
            for (int k = 0; k < 16; k++) {
                float4 mv0 = *(const float4*)&As[k*68 + tr*8];
                float4 mv1 = *(const float4*)&As[k*68 + tr*8 + 4];
                float4 nv0 = *(const float4*)&Bs[k*256 + tc*8];
                float4 nv1 = *(const float4*)&Bs[k*256 + tc*8 + 4];
                float rm[8] = {mv0.x,mv0.y,mv0.z,mv0.w, mv1.x,mv1.y,mv1.z,mv1.w};
                float rn[8] = {nv0.x,nv0.y,nv0.z,nv0.w, nv1.x,nv1.y,nv1.z,nv1.w};
#pragma unroll
                for (int i = 0; i < 8; i++)
#pragma unroll
                    for (int j = 0; j < 8; j++)
                        acc[i][j] = fmaf(rm[i], rn[j], acc[i][j]);
            }
            __syncthreads();
        }
    }

    // ---- interaction features: qint_p = c_i*c_j + s_i*s_j over selected cols
    float* smc = buf;                 // [64][16]  c at +j, s at +8+j   (1024)
    float* smW = buf + 1024;          // [28][256]                      (7168)
    float* smq = buf + 8192;          // [64][28]                       (1792)

    for (int e = tid; e < 512; e += 256) {
        int r = e >> 3, j = e & 7;
        int m = row0 + r;
        int ci = g_idx[j];
        float cv = 0.f, sv = 0.f;
        if (m < N_ROWS) {
            size_t o = (size_t)m * C_DIM + ci;
            cv = g_qc[o]; sv = g_qs[o];
        }
        smc[r*16 + j]     = cv;
        smc[r*16 + 8 + j] = sv;
    }
#pragma unroll 4
    for (int p = 0; p < NPAIR; p++)
        smW[p*256 + tid] = Wout[(size_t)tid * QDIM_V + 2048 + p];
    __syncthreads();

    for (int e = tid; e < 64*NPAIR; e += 256) {
        int r = e / NPAIR, p = e - r*NPAIR;
        int i = c_iu[p], j = c_ju[p];
        smq[r*NPAIR + p] = smc[r*16+i]*smc[r*16+j] + smc[r*16+8+i]*smc[r*16+8+j];
    }
    __syncthreads();

#pragma unroll 4
    for (int p = 0; p < NPAIR; p++) {
        float wn[8];
#pragma unroll
        for (int j = 0; j < 8; j++) wn[j] = smW[p*256 + tc*8 + j];
#pragma unroll
        for (int i = 0; i < 8; i++) {
            float qi = smq[(tr*8+i)*NPAIR + p];
#pragma unroll
            for (int j = 0; j < 8; j++) acc[i][j] = fmaf(qi, wn[j], acc[i][j]);
        }
    }

    // ---- alpha, bias, fused output LayerNorm (warp owns full 256-wide rows)
    const float alpha = alphap[0];
    float bo[8], go8[8], ob8[8];
#pragma unroll
    for (int j = 0; j < 8; j++) {
        int col = tc*8 + j;
        bo[j] = bout[col]; go8[j] = og[col]; ob8[j] = ob[col];
    }
#pragma unroll
    for (int i = 0; i < 8; i++)
#pragma unroll
        for (int j = 0; j < 8; j++)
            acc[i][j] = acc[i][j] * alpha + bo[j];

#pragma unroll
    for (int i = 0; i < 8; i++) {
        int m = row0 + tr*8 + i;
        float s = 0.f, s2 = 0.f;
#pragma unroll
        for (int j = 0; j < 8; j++) { s += acc[i][j]; s2 += acc[i][j]*acc[i][j]; }
#pragma unroll
        for (int off = 16; off; off >>= 1) {
            s  += __shfl_xor_sync(0xffffffffu, s,  off);
            s2 += __shfl_xor_sync(0xffffffffu, s2, off);
        }
        float mu   = s * (1.f / OUT_DIM);
        float rstd = rsqrtf(s2 * (1.f / OUT_DIM) - mu*mu + LN_EPS);
        if (m < N_ROWS) {
            float o0[8];
#pragma unroll
            for (int j = 0; j < 8; j++) o0[j] = (acc[i][j] - mu) * rstd * go8[j] + ob8[j];
            float4* op = (float4*)(Out + (size_t)m * OUT_DIM + tc*8);
            op[0] = make_float4(o0[0],o0[1],o0[2],o0[3]);
            op[1] = make_float4(o0[4],o0[5],o0[6],o0[7]);
        }
    }
}

// ---------------------------------------------------------------------------
// Launch sequence (default stream -> graph-capturable, fully ordered)
// ---------------------------------------------------------------------------
extern "C" void kernel_launch(void* const* d_in, const int* in_sizes, int n_in,
                              void* d_out, int out_size) {
    const float* x     = (const float*)d_in[0];
    const float* Wproj = (const float*)d_in[1];
    const float* bproj = (const float*)d_in[2];
    const float* lng   = (const float*)d_in[3];
    const float* lnb   = (const float*)d_in[4];
    const float* alpha = (const float*)d_in[5];
    const float* Wout  = (const float*)d_in[6];
    const float* bout  = (const float*)d_in[7];
    const float* olng  = (const float*)d_in[8];
    const float* olnb  = (const float*)d_in[9];
    float* out = (float*)d_out;

    (void)in_sizes; (void)n_in; (void)out_size;

    zero_stats_kernel<<<1, 1024>>>();

    dim3 g1(C_DIM / 128, (N_ROWS + 127) / 128);   // (8, 782)
    gemm1_kernel<<<g1, 256>>>(x, Wproj, bproj);

    ln_phi_kernel<<<(N_ROWS + 127) / 128, 256>>>(lng, lnb);

    topk_kernel<<<1, 256>>>();

    gemm2_kernel<<<(N_ROWS + 63) / 64, 256>>>(Wout, bout, alpha, olng, olnb, out);
}

// round 6
// speedup vs baseline: 1.7705x; 1.7705x over previous
#include <cuda_runtime.h>
#include <cuda_bf16.h>
#include <cstdint>

#define N_ROWS  100000
#define C_DIM   1024
#define OUT_DIM 256
#define TOPK_K  8
#define NPAIR   28
#define QDIM_V  2076
#define LN_EPS  1e-5f

// ---------------------------------------------------------------------------
// Device-global scratch (no cudaMalloc allowed)
// ---------------------------------------------------------------------------
__device__ float g_z [(size_t)N_ROWS * C_DIM];    // GEMM1 output (pre-LN)
__device__ float g_qc[(size_t)N_ROWS * C_DIM];    // cos(pi*tanh(z_ln))
__device__ float g_qs[(size_t)N_ROWS * C_DIM];    // sin(pi*tanh(z_ln))
__device__ float g_q [(size_t)N_ROWS * OUT_DIM];  // GEMM2 raw sums
__device__ float g_colsum [C_DIM];
__device__ float g_colsum2[C_DIM];
__device__ int   g_idx[TOPK_K];

// np.triu_indices(8, 1)
__constant__ int c_iu[NPAIR] = {0,0,0,0,0,0,0, 1,1,1,1,1,1, 2,2,2,2,2, 3,3,3,3, 4,4,4, 5,5, 6};
__constant__ int c_ju[NPAIR] = {1,2,3,4,5,6,7, 2,3,4,5,6,7, 3,4,5,6,7, 4,5,6,7, 5,6,7, 6,7, 7};

// ---------------------------------------------------------------------------
// Helpers
// ---------------------------------------------------------------------------
__device__ __forceinline__ uint32_t smem_u32(const void* p) {
    uint32_t a;
    asm("{ .reg .u64 t; cvta.to.shared.u64 t, %1; cvt.u32.u64 %0, t; }" : "=r"(a) : "l"(p));
    return a;
}
#define SWZ(o) ((o) ^ (((o) >> 3) & 0x70))

__device__ __forceinline__ void mma16816(float* d, const uint32_t* a, const uint32_t* b) {
    asm volatile("mma.sync.aligned.m16n8k16.row.col.f32.bf16.bf16.f32 "
        "{%0,%1,%2,%3}, {%4,%5,%6,%7}, {%8,%9}, {%0,%1,%2,%3};"
        : "+f"(d[0]), "+f"(d[1]), "+f"(d[2]), "+f"(d[3])
        : "r"(a[0]), "r"(a[1]), "r"(a[2]), "r"(a[3]), "r"(b[0]), "r"(b[1]));
}
__device__ __forceinline__ void ldsm_x4(uint32_t* r, uint32_t addr) {
    asm volatile("ldmatrix.sync.aligned.m8n8.x4.shared.b16 {%0,%1,%2,%3}, [%4];"
        : "=r"(r[0]), "=r"(r[1]), "=r"(r[2]), "=r"(r[3]) : "r"(addr));
}

// split fp32 x4 into bf16 hi/lo x4 (packed, memory order)
__device__ __forceinline__ void split4(float4 v, uint2& hi, uint2& lo) {
    __nv_bfloat16 h0 = __float2bfloat16_rn(v.x);
    __nv_bfloat16 h1 = __float2bfloat16_rn(v.y);
    __nv_bfloat16 h2 = __float2bfloat16_rn(v.z);
    __nv_bfloat16 h3 = __float2bfloat16_rn(v.w);
    __nv_bfloat16 l0 = __float2bfloat16_rn(v.x - __bfloat162float(h0));
    __nv_bfloat16 l1 = __float2bfloat16_rn(v.y - __bfloat162float(h1));
    __nv_bfloat16 l2 = __float2bfloat16_rn(v.z - __bfloat162float(h2));
    __nv_bfloat16 l3 = __float2bfloat16_rn(v.w - __bfloat162float(h3));
    hi.x = (uint32_t)__bfloat16_as_ushort(h0) | ((uint32_t)__bfloat16_as_ushort(h1) << 16);
    hi.y = (uint32_t)__bfloat16_as_ushort(h2) | ((uint32_t)__bfloat16_as_ushort(h3) << 16);
    lo.x = (uint32_t)__bfloat16_as_ushort(l0) | ((uint32_t)__bfloat16_as_ushort(l1) << 16);
    lo.y = (uint32_t)__bfloat16_as_ushort(l2) | ((uint32_t)__bfloat16_as_ushort(l3) << 16);
}

// ---------------------------------------------------------------------------
// Split-bf16 mma.sync GEMM: block 128x128, 512 threads, warp tile 32x32.
// A*B ~= Ah*Bh + Ah*Bl + Al*Bh  (fp32 accumulators)
// smem stage (64KB): Ah@0 | Al@16K | Bh@32K | Bl@48K, SW128 swizzle, K-chunk 64.
// G2=false: g_z = x @ Wproj^T + bias.  G2=true: g_q = [Qc|Qs] @ Wout[:, :2048]^T
// ---------------------------------------------------------------------------
template<int KT, bool G2>
__global__ void __launch_bounds__(512, 1)
gemm_mma(const float* __restrict__ A0, const float* __restrict__ B0,
         const float* __restrict__ bias)
{
    extern __shared__ char smem[];
    const uint32_t sbase = smem_u32(smem);
    const int tid  = threadIdx.x;
    const int lane = tid & 31;
    const int warp = tid >> 5;
    const int wm   = warp >> 2;            // 0..3
    const int wn   = warp & 3;             // 0..3
    const int n0   = blockIdx.x * 128;
    const long m0  = (long)blockIdx.y * 128;
    const long sA  = C_DIM;
    const long sB  = G2 ? QDIM_V : C_DIM;

    float acc[2][4][4];
#pragma unroll
    for (int mt = 0; mt < 2; mt++)
#pragma unroll
        for (int nt = 0; nt < 4; nt++)
#pragma unroll
            for (int j = 0; j < 4; j++) acc[mt][nt][j] = 0.f;

    // ldmatrix per-lane address precompute (swizzle XOR depends only on row)
    const int a_r  = lane & 15;
    const int a_kb = (lane >> 4) << 4;
    const int b_r  = (lane & 7) | ((lane >> 4) << 3);
    const int b_kb = ((lane >> 3) & 1) << 4;
    uint32_t aoff[2], axr[2], boff[2], bxr[2];
#pragma unroll
    for (int mt = 0; mt < 2; mt++) {
        uint32_t o = (uint32_t)((wm * 32 + mt * 16 + a_r) * 128 + a_kb);
        axr[mt] = (o >> 3) & 0x70; aoff[mt] = o;
    }
#pragma unroll
    for (int bt = 0; bt < 2; bt++) {
        uint32_t o = (uint32_t)((wn * 32 + bt * 16 + b_r) * 128 + b_kb);
        bxr[bt] = (o >> 3) & 0x70; boff[bt] = o;
    }

    for (int kt = 0; kt < KT; kt++) {
        // ---- fill: fp32 gmem -> bf16 hi/lo swizzled smem ----
        const float* Ap; long acol;
        if (G2) {
            if (kt < KT / 2) { Ap = (const float*)g_qc; acol = (long)kt * 64; }
            else             { Ap = (const float*)g_qs; acol = (long)(kt - KT / 2) * 64; }
        } else { Ap = A0; acol = (long)kt * 64; }
        const long bcol = (long)kt * 64;
#pragma unroll
        for (int i = 0; i < 4; i++) {
            int e = tid + i * 512, r = e >> 4, c = e & 15;
            long arow = m0 + r;
            float4 va = (arow < N_ROWS)
                ? __ldg((const float4*)(Ap + arow * sA + acol + c * 4))
                : make_float4(0.f, 0.f, 0.f, 0.f);
            float4 vb = __ldg((const float4*)(B0 + (long)(n0 + r) * sB + bcol + c * 4));
            uint32_t off = SWZ((uint32_t)(r * 128 + c * 8));
            uint2 hi, lo;
            split4(va, hi, lo);
            *(uint2*)(smem + off)         = hi;
            *(uint2*)(smem + 16384 + off) = lo;
            split4(vb, hi, lo);
            *(uint2*)(smem + 32768 + off) = hi;
            *(uint2*)(smem + 49152 + off) = lo;
        }
        __syncthreads();

        // ---- compute: 4 k16 steps x 3 split terms ----
#pragma unroll
        for (int ks = 0; ks < 4; ks++) {
            uint32_t ah[2][4], al[2][4], bh[4][2], bl[4][2];
#pragma unroll
            for (int mt = 0; mt < 2; mt++) {
                uint32_t ad = sbase + ((aoff[mt] + ks * 32) ^ axr[mt]);
                ldsm_x4(ah[mt], ad);
                ldsm_x4(al[mt], ad + 16384);
            }
#pragma unroll
            for (int bt = 0; bt < 2; bt++) {
                uint32_t bd = sbase + 32768 + ((boff[bt] + ks * 32) ^ bxr[bt]);
                uint32_t q[4];
                ldsm_x4(q, bd);
                bh[2*bt][0] = q[0]; bh[2*bt][1] = q[1];
                bh[2*bt+1][0] = q[2]; bh[2*bt+1][1] = q[3];
                ldsm_x4(q, bd + 16384);
                bl[2*bt][0] = q[0]; bl[2*bt][1] = q[1];
                bl[2*bt+1][0] = q[2]; bl[2*bt+1][1] = q[3];
            }
#pragma unroll
            for (int mt = 0; mt < 2; mt++)
#pragma unroll
                for (int nt = 0; nt < 4; nt++) {
                    mma16816(acc[mt][nt], ah[mt], bh[nt]);
                    mma16816(acc[mt][nt], ah[mt], bl[nt]);
                    mma16816(acc[mt][nt], al[mt], bh[nt]);
                }
        }
        __syncthreads();
    }

    // ---- epilogue: write fp32 (optionally + bias) ----
    float* Outp = G2 ? (float*)g_q : (float*)g_z;
    const long sOut = G2 ? OUT_DIM : C_DIM;
    const int qr = lane >> 2;
    const int qc = (lane & 3) * 2;
#pragma unroll
    for (int mt = 0; mt < 2; mt++)
#pragma unroll
        for (int nt = 0; nt < 4; nt++) {
            long m = m0 + wm * 32 + mt * 16 + qr;
            int  n = n0 + wn * 32 + nt * 8 + qc;
            float2 bv = make_float2(0.f, 0.f);
            if (!G2) bv = *(const float2*)(bias + n);
            if (m < N_ROWS) {
                float2 v = make_float2(acc[mt][nt][0] + bv.x, acc[mt][nt][1] + bv.y);
                *(float2*)(Outp + m * sOut + n) = v;
            }
            if (m + 8 < N_ROWS) {
                float2 v = make_float2(acc[mt][nt][2] + bv.x, acc[mt][nt][3] + bv.y);
                *(float2*)(Outp + (m + 8) * sOut + n) = v;
            }
        }
}

// ---------------------------------------------------------------------------
// Kernel 0: zero per-replay column accumulators
// ---------------------------------------------------------------------------
__global__ void zero_stats_kernel() {
    int t = threadIdx.x;
    if (t < C_DIM) { g_colsum[t] = 0.f; g_colsum2[t] = 0.f; }
}

// ---------------------------------------------------------------------------
// Kernel 2: row LayerNorm + phi -> (cos,sin), fused column stats
// ---------------------------------------------------------------------------
__global__ __launch_bounds__(256)
void ln_phi_kernel(const float* __restrict__ lng, const float* __restrict__ lnb)
{
    const int tid  = threadIdx.x;
    const int lane = tid & 31;
    const int warp = tid >> 5;
    const int row0 = blockIdx.x * 128;
    const int rowEnd = min(row0 + 128, N_ROWS);

    __shared__ float redS[8], redS2[8];
    __shared__ float sMu, sRstd;

    float gv[4], bv[4];
#pragma unroll
    for (int j = 0; j < 4; j++) { gv[j] = lng[tid + j*256]; bv[j] = lnb[tid + j*256]; }

    float cs[4]  = {0.f,0.f,0.f,0.f};
    float cs2[4] = {0.f,0.f,0.f,0.f};

    for (int row = row0; row < rowEnd; row++) {
        const float* zr = g_z + (size_t)row * C_DIM;
        float v[4]; float s = 0.f, s2 = 0.f;
#pragma unroll
        for (int j = 0; j < 4; j++) {
            v[j] = zr[tid + j*256];
            s += v[j]; s2 += v[j]*v[j];
        }
#pragma unroll
        for (int off = 16; off; off >>= 1) {
            s  += __shfl_xor_sync(0xffffffffu, s,  off);
            s2 += __shfl_xor_sync(0xffffffffu, s2, off);
        }
        if (lane == 0) { redS[warp] = s; redS2[warp] = s2; }
        __syncthreads();
        if (tid == 0) {
            float S = 0.f, S2 = 0.f;
#pragma unroll
            for (int w = 0; w < 8; w++) { S += redS[w]; S2 += redS2[w]; }
            float mu = S * (1.f / C_DIM);
            sMu = mu;
            sRstd = rsqrtf(S2 * (1.f / C_DIM) - mu*mu + LN_EPS);
        }
        __syncthreads();
        const float mu = sMu, rstd = sRstd;
        float* qcr = g_qc + (size_t)row * C_DIM;
        float* qsr = g_qs + (size_t)row * C_DIM;
#pragma unroll
        for (int j = 0; j < 4; j++) {
            float zl = (v[j] - mu) * rstd * gv[j] + bv[j];
            cs[j] += zl; cs2[j] += zl * zl;
            float phi = 3.14159265358979323846f * tanhf(zl);
            float sn, cn; sincosf(phi, &sn, &cn);
            qcr[tid + j*256] = cn;
            qsr[tid + j*256] = sn;
        }
    }
#pragma unroll
    for (int j = 0; j < 4; j++) {
        atomicAdd(&g_colsum [tid + j*256], cs[j]);
        atomicAdd(&g_colsum2[tid + j*256], cs2[j]);
    }
}

// ---------------------------------------------------------------------------
// Kernel 3: column variance (ddof=1) + top-8
// ---------------------------------------------------------------------------
__global__ void topk_kernel()
{
    __shared__ float svar[C_DIM];
    const int tid = threadIdx.x;
    for (int c = tid; c < C_DIM; c += 256) {
        float s = g_colsum[c], s2 = g_colsum2[c];
        float mean = s * (1.f / N_ROWS);
        svar[c] = (s2 - s * mean) * (1.f / (N_ROWS - 1));
    }
    __syncthreads();
    if (tid < 32) {
        for (int p = 0; p < TOPK_K; p++) {
            float bvv = -3.0e38f; int bii = C_DIM;
            for (int c = tid; c < C_DIM; c += 32) {
                float vv = svar[c];
                if (vv > bvv || (vv == bvv && c < bii)) { bvv = vv; bii = c; }
            }
#pragma unroll
            for (int off = 16; off; off >>= 1) {
                float ov = __shfl_xor_sync(0xffffffffu, bvv, off);
                int   oi = __shfl_xor_sync(0xffffffffu, bii, off);
                if (ov > bvv || (ov == bvv && oi < bii)) { bvv = ov; bii = oi; }
            }
            if (tid == 0) { g_idx[p] = bii; svar[bii] = -3.0e38f; }
            __syncwarp();
        }
    }
}

// ---------------------------------------------------------------------------
// Kernel 5: interactions + alpha + bias + fused output LN
// out = LN( alpha*(g_q + qint @ Wi^T) + b_out )
// ---------------------------------------------------------------------------
__global__ __launch_bounds__(256)
void interact_ln_kernel(const float* __restrict__ Wout,
                        const float* __restrict__ bout,
                        const float* __restrict__ alphap,
                        const float* __restrict__ og,
                        const float* __restrict__ ob,
                        float* __restrict__ Out)
{
    __shared__ float sW[NPAIR * 256];   // [p][n]
    __shared__ float sb_[256], sg_[256], sob_[256];
    const int tid  = threadIdx.x;
    const int lane = tid & 31;
    const int warp = tid >> 5;

    for (int e = tid; e < NPAIR * 256; e += 256) {
        int p = e >> 8, n = e & 255;
        sW[p * 256 + n] = __ldg(&Wout[(long)n * QDIM_V + 2048 + p]);
    }
    sb_[tid] = bout[tid]; sg_[tid] = og[tid]; sob_[tid] = ob[tid];
    __syncthreads();

    const float alpha = __ldg(alphap);
    int idx8[8];
#pragma unroll
    for (int j = 0; j < 8; j++) idx8[j] = g_idx[j];

    const long rowBase = (long)blockIdx.x * 128 + warp * 16;
    for (int i = 0; i < 16; i++) {
        long row = rowBase + i;
        if (row >= N_ROWS) break;

        float qc8[8], qs8[8];
#pragma unroll
        for (int j = 0; j < 8; j++) {
            qc8[j] = __ldg(&g_qc[row * C_DIM + idx8[j]]);
            qs8[j] = __ldg(&g_qs[row * C_DIM + idx8[j]]);
        }
        float qint[NPAIR];
#pragma unroll
        for (int p = 0; p < NPAIR; p++)
            qint[p] = qc8[c_iu[p]] * qc8[c_ju[p]] + qs8[c_iu[p]] * qs8[c_ju[p]];

        const float* gq = g_q + row * OUT_DIM + lane * 8;
        float4 v0 = ((const float4*)gq)[0];
        float4 v1 = ((const float4*)gq)[1];
        float v[8] = {v0.x, v0.y, v0.z, v0.w, v1.x, v1.y, v1.z, v1.w};
#pragma unroll
        for (int p = 0; p < NPAIR; p++) {
            float q = qint[p];
            const float4* wp = (const float4*)(sW + p * 256 + lane * 8);
            float4 w0 = wp[0], w1 = wp[1];
            v[0] = fmaf(q, w0.x, v[0]); v[1] = fmaf(q, w0.y, v[1]);
            v[2] = fmaf(q, w0.z, v[2]); v[3] = fmaf(q, w0.w, v[3]);
            v[4] = fmaf(q, w1.x, v[4]); v[5] = fmaf(q, w1.y, v[5]);
            v[6] = fmaf(q, w1.z, v[6]); v[7] = fmaf(q, w1.w, v[7]);
        }
        float s = 0.f, s2 = 0.f;
#pragma unroll
        for (int j = 0; j < 8; j++) {
            float val = fmaf(alpha, v[j], sb_[lane * 8 + j]);
            v[j] = val; s += val; s2 += val * val;
        }
#pragma unroll
        for (int off = 16; off; off >>= 1) {
            s  += __shfl_xor_sync(0xffffffffu, s,  off);
            s2 += __shfl_xor_sync(0xffffffffu, s2, off);
        }
        float mu   = s * (1.f / OUT_DIM);
        float rstd = rsqrtf(s2 * (1.f / OUT_DIM) - mu * mu + LN_EPS);
        float o[8];
#pragma unroll
        for (int j = 0; j < 8; j++)
            o[j] = (v[j] - mu) * rstd * sg_[lane * 8 + j] + sob_[lane * 8 + j];
        float4* op = (float4*)(Out + row * OUT_DIM + lane * 8);
        op[0] = make_float4(o[0], o[1], o[2], o[3]);
        op[1] = make_float4(o[4], o[5], o[6], o[7]);
    }
}

// ---------------------------------------------------------------------------
// Launch sequence
// ---------------------------------------------------------------------------
extern "C" void kernel_launch(void* const* d_in, const int* in_sizes, int n_in,
                              void* d_out, int out_size) {
    const float* x     = (const float*)d_in[0];
    const float* Wproj = (const float*)d_in[1];
    const float* bproj = (const float*)d_in[2];
    const float* lng   = (const float*)d_in[3];
    const float* lnb   = (const float*)d_in[4];
    const float* alpha = (const float*)d_in[5];
    const float* Wout  = (const float*)d_in[6];
    const float* bout  = (const float*)d_in[7];
    const float* olng  = (const float*)d_in[8];
    const float* olnb  = (const float*)d_in[9];
    float* out = (float*)d_out;

    (void)in_sizes; (void)n_in; (void)out_size;

    const int SMEM_GEMM = 65536;
    cudaFuncSetAttribute((const void*)gemm_mma<16, false>,
                         cudaFuncAttributeMaxDynamicSharedMemorySize, SMEM_GEMM);
    cudaFuncSetAttribute((const void*)gemm_mma<32, true>,
                         cudaFuncAttributeMaxDynamicSharedMemorySize, SMEM_GEMM);

    const int MTILES = (N_ROWS + 127) / 128;   // 782

    zero_stats_kernel<<<1, 1024>>>();

    // GEMM1: g_z = x @ Wproj^T + bproj
    gemm_mma<16, false><<<dim3(8, MTILES), 512, SMEM_GEMM>>>(x, Wproj, bproj);

    ln_phi_kernel<<<MTILES, 256>>>(lng, lnb);

    topk_kernel<<<1, 256>>>();

    // GEMM2: g_q = [Qc|Qs] @ Wout[:, 0:2048]^T
    gemm_mma<32, true><<<dim3(2, MTILES), 512, SMEM_GEMM>>>(nullptr, Wout, nullptr);

    // out = LN(alpha*(g_q + qint@Wi^T) + bout)
    interact_ln_kernel<<<MTILES, 256>>>(Wout, bout, alpha, olng, olnb, out);
}